// round 8
// baseline (speedup 1.0000x reference)
#include <cuda_runtime.h>
#include <math.h>
#include <stdint.h>

typedef unsigned long long ull;
typedef unsigned short u16;

// ---------------- problem constants ----------------
constexpr int kB = 2, kT = 98304, kS = 128, kHOP = 768, kNCB = 14;
constexpr int kDIM = 512, kVOC = 1024, kCH3 = kNCB * kDIM;   // 7168
constexpr long kL = 97537;
constexpr int kBS = kB * kS;        // 256
constexpr long BIGL = 1L << 40;

// ---------------- device scratch ----------------
// bf16 hi/lo operand planes (16B-aligned for vector LDG)
__device__ __align__(16) u16 g_S1h [kBS * 1280],  g_S1l [kBS * 1280];
__device__ __align__(16) u16 g_ew2h[512 * 1280],  g_ew2l[512 * 1280];
__device__ __align__(16) u16 g_Xh  [kBS * 1536],  g_Xl  [kBS * 1536];
__device__ __align__(16) u16 g_ew3h[kCH3 * 1536], g_ew3l[kCH3 * 1536];
__device__ __align__(16) u16 g_embh[kNCB * kBS * kDIM], g_embl[kNCB * kBS * kDIM];
__device__ __align__(16) u16 g_cbh [kNCB * kVOC * kDIM], g_cbl [kNCB * kVOC * kDIM];
__device__ __align__(16) u16 g_dw1Th[2560L * kCH3], g_dw1Tl[2560L * kCH3];
__device__ __align__(16) u16 g_W2h [256 * 2560],  g_W2l [256 * 2560];
__device__ __align__(16) u16 g_awh [kBS * 6656],  g_awl [kBS * 6656];
// f32 intermediates
__device__ float g_h2p [8 * kBS * 512];
__device__ float g_C2p [7 * kBS * 2560];
__device__ float g_C3p [4 * 2304 * 256];
__device__ float g_cbn [kNCB * kVOC];
__device__ ull   g_best[kNCB * kBS];
__device__ float g_bg2 [256];

// =================== HMMA bf16 split GEMM (preconverted operands) ===================
constexpr int KC = 32;
constexpr int PITCH_B = 80;
constexpr int TILE_BYTES = 128 * PITCH_B;
constexpr int STAGE = 4 * TILE_BYTES;
constexpr int SMEM_DYN = 2 * STAGE;              // 81920

__device__ __forceinline__ uint32_t s2u(const void* p) {
    uint32_t a;
    asm("{ .reg .u64 t; cvta.to.shared.u64 t, %1; cvt.u32.u64 %0, t; }" : "=r"(a) : "l"(p));
    return a;
}
__device__ __forceinline__ uint32_t pkbf2(float lo, float hi) {
    uint32_t r;
    asm("cvt.rn.bf16x2.f32 %0, %1, %2;" : "=r"(r) : "f"(hi), "f"(lo));
    return r;
}
// split pair (a,b) -> packed hi u32 + packed lo u32 (elementwise x = hi + lo)
__device__ __forceinline__ void split2(float a, float b, uint32_t& ph, uint32_t& pl) {
    ph = pkbf2(a, b);
    float ha = __uint_as_float(ph << 16);
    float hb = __uint_as_float(ph & 0xffff0000u);
    pl = pkbf2(a - ha, b - hb);
}
__device__ __forceinline__ void split1(float x, u16& h, u16& l) {
    uint32_t ph, pl; split2(x, x, ph, pl);
    h = (u16)(ph & 0xffff); l = (u16)(pl & 0xffff);
}
__device__ __forceinline__ void ldsm4(uint32_t a, uint32_t& r0, uint32_t& r1,
                                      uint32_t& r2, uint32_t& r3) {
    asm volatile("ldmatrix.sync.aligned.m8n8.x4.shared.b16 {%0,%1,%2,%3},[%4];"
                 : "=r"(r0), "=r"(r1), "=r"(r2), "=r"(r3) : "r"(a));
}
__device__ __forceinline__ void mma16816(float* d, const uint32_t* a, const uint32_t* b) {
    asm volatile(
        "mma.sync.aligned.m16n8k16.row.col.f32.bf16.bf16.f32 "
        "{%0,%1,%2,%3},{%4,%5,%6,%7},{%8,%9},{%0,%1,%2,%3};"
        : "+f"(d[0]), "+f"(d[1]), "+f"(d[2]), "+f"(d[3])
        : "r"(a[0]), "r"(a[1]), "r"(a[2]), "r"(a[3]), "r"(b[0]), "r"(b[1]));
}
__device__ __forceinline__ ull packkey(float f, int n) {
    uint32_t b = __float_as_uint(f);
    uint32_t key = (b & 0x80000000u) ? ~b : (b | 0x80000000u);
    return ((ull)key << 32) | (uint32_t)n;
}
__device__ __forceinline__ ull umin2(ull a, ull b) { return a < b ? a : b; }

// C[m,n] = sum_k A(m)[k]*B(n)[k], all operands preconverted bf16 hi/lo, NT layout.
// GATHER=1: A row m of codebook cbk=(kglob>>9) uses code g_best[cbk*256+m] into cb planes.
// A row m elem base = (m/adiv)*aout + (m%adiv)*ain.  z: A+=zA, B+=zB, C+=zC, kbase=z*zK.
// Epilogue: best!=null -> fused VQ argmin; Cbh!=null -> bf16 hi/lo dual write (+bias);
// else f32 C write (+bias,relu). C elem = (n0/cdiv)*cout + row*ldc + n0%cdiv + col.
template <int GATHER>
__global__ __launch_bounds__(256, 1)
void hmma_gemm(const u16* __restrict__ Ah, const u16* __restrict__ Al,
               const u16* __restrict__ Bh, const u16* __restrict__ Bl,
               float* __restrict__ C, int Klen, int ldb,
               long adiv, long aout, long ain, long zA, long zB, long zC, long zK,
               int ldc, long cdiv, long cout, const float* __restrict__ bias, int relu,
               const float* __restrict__ cbn, ull* __restrict__ best,
               u16* __restrict__ Cbh, u16* __restrict__ Cbl) {
    extern __shared__ __align__(16) char smem[];
    Ah += (long)blockIdx.z * zA; Al += (long)blockIdx.z * zA;
    Bh += (long)blockIdx.z * zB; Bl += (long)blockIdx.z * zB;
    C  += (long)blockIdx.z * zC;
    long kbase = (long)blockIdx.z * zK;
    int m0 = blockIdx.y * 128, n0 = blockIdx.x * 128;
    int tid = threadIdx.x, lane = tid & 31, wid = tid >> 5;
    int wm = wid & 1, wn = wid >> 1;
    uint32_t sbase = s2u(smem);

    // producer mapping: each thread owns one (row, plane), 4x16B segments
    int prow = tid & 127, ppl = tid >> 7;
    const u16* Ap = ppl ? Al : Ah;
    const u16* Bp = ppl ? Bl : Bh;
    long mrow = m0 + prow;
    long abase = GATHER ? 0 : (mrow / adiv) * aout + (mrow % adiv) * ain;
    long bbase = (long)(n0 + prow) * ldb;
    uint4 ra[4], rb[4];

#define LOADP(kc) {                                                          \
    long asrc;                                                               \
    if (GATHER) {                                                            \
        long kg = (kc);                                                      \
        int cbk = (int)(kg >> 9);                                            \
        uint32_t code = (uint32_t)g_best[cbk * 256 + mrow];                  \
        asrc = ((long)(cbk * 1024) + code) * 512 + (kg & 511);               \
    } else asrc = abase + (kc);                                              \
    _Pragma("unroll")                                                        \
    for (int s = 0; s < 4; s++) ra[s] = *(const uint4*)(Ap + asrc + s * 8);  \
    long bsrc = bbase + (kc);                                                \
    _Pragma("unroll")                                                        \
    for (int s = 0; s < 4; s++) rb[s] = *(const uint4*)(Bp + bsrc + s * 8);  \
    }
#define STSP(buf) {                                                          \
    uint32_t da = sbase + (buf) * STAGE + ppl * TILE_BYTES + prow * PITCH_B; \
    uint32_t db_ = da + 2 * TILE_BYTES;                                      \
    _Pragma("unroll")                                                        \
    for (int s = 0; s < 4; s++) {                                            \
        asm volatile("st.shared.v4.b32 [%0],{%1,%2,%3,%4};" ::               \
            "r"(da + s * 16), "r"(ra[s].x), "r"(ra[s].y), "r"(ra[s].z), "r"(ra[s].w)); \
        asm volatile("st.shared.v4.b32 [%0],{%1,%2,%3,%4};" ::               \
            "r"(db_ + s * 16), "r"(rb[s].x), "r"(rb[s].y), "r"(rb[s].z), "r"(rb[s].w)); \
    } }

    float acc[4][4][4];
    #pragma unroll
    for (int i = 0; i < 4; i++)
        #pragma unroll
        for (int j = 0; j < 4; j++)
            #pragma unroll
            for (int r = 0; r < 4; r++) acc[i][j][r] = 0.f;

    LOADP(kbase)
    STSP(0)
    __syncthreads();

    int T = Klen / KC;
    int j8 = lane >> 3, r8 = lane & 7;
    for (int t = 0; t < T; t++) {
        int cur = t & 1;
        if (t + 1 < T) LOADP(kbase + (long)(t + 1) * KC)
        uint32_t uA = sbase + cur * STAGE;
        uint32_t uB = uA + 2 * TILE_BYTES;
        #pragma unroll
        for (int ks = 0; ks < 2; ks++) {
            uint32_t ah[4][4], al[4][4], bh[4][2], bl[4][2];
            #pragma unroll
            for (int mf = 0; mf < 4; mf++) {
                uint32_t off = (uint32_t)((wm * 64 + mf * 16 + ((j8 & 1) << 3) + r8) * PITCH_B
                                          + ks * 32 + ((j8 >> 1) << 4));
                ldsm4(uA + off, ah[mf][0], ah[mf][1], ah[mf][2], ah[mf][3]);
                ldsm4(uA + TILE_BYTES + off, al[mf][0], al[mf][1], al[mf][2], al[mf][3]);
            }
            #pragma unroll
            for (int fp = 0; fp < 2; fp++) {
                uint32_t off = (uint32_t)((wn * 32 + fp * 16 + ((j8 >> 1) << 3) + r8) * PITCH_B
                                          + ks * 32 + ((j8 & 1) << 4));
                uint32_t t0, t1, t2, t3;
                ldsm4(uB + off, t0, t1, t2, t3);
                bh[fp * 2][0] = t0; bh[fp * 2][1] = t1;
                bh[fp * 2 + 1][0] = t2; bh[fp * 2 + 1][1] = t3;
                ldsm4(uB + TILE_BYTES + off, t0, t1, t2, t3);
                bl[fp * 2][0] = t0; bl[fp * 2][1] = t1;
                bl[fp * 2 + 1][0] = t2; bl[fp * 2 + 1][1] = t3;
            }
            #pragma unroll
            for (int mf = 0; mf < 4; mf++)
                #pragma unroll
                for (int nf = 0; nf < 4; nf++) {
                    mma16816(acc[mf][nf], ah[mf], bh[nf]);
                    mma16816(acc[mf][nf], ah[mf], bl[nf]);
                    mma16816(acc[mf][nf], al[mf], bh[nf]);
                }
        }
        if (t + 1 < T) STSP(1 - cur)
        __syncthreads();
    }

    int mrow_base = m0 + wm * 64 + (lane >> 2);
    int ncol_base = wn * 32 + (lane & 3) * 2;

    if (best) {                              // fused VQ argmin
        float cv[8];
        #pragma unroll
        for (int nf = 0; nf < 4; nf++) {
            int ncol = ncol_base + nf * 8;
            cv[nf * 2 + 0] = cbn[(long)blockIdx.z * kVOC + n0 + ncol];
            cv[nf * 2 + 1] = cbn[(long)blockIdx.z * kVOC + n0 + ncol + 1];
        }
        #pragma unroll
        for (int mf = 0; mf < 4; mf++)
            #pragma unroll
            for (int h = 0; h < 2; h++) {
                ull bp = ~0ull;
                #pragma unroll
                for (int nf = 0; nf < 4; nf++) {
                    int ncol = ncol_base + nf * 8;
                    float d0 = cv[nf * 2 + 0] - 2.f * acc[mf][nf][h * 2 + 0];
                    float d1 = cv[nf * 2 + 1] - 2.f * acc[mf][nf][h * 2 + 1];
                    bp = umin2(bp, umin2(packkey(d0, n0 + ncol), packkey(d1, n0 + ncol + 1)));
                }
                bp = umin2(bp, (ull)__shfl_xor_sync(0xffffffffu, (long long)bp, 1));
                bp = umin2(bp, (ull)__shfl_xor_sync(0xffffffffu, (long long)bp, 2));
                if ((lane & 3) == 0)
                    atomicMin(&best[(long)blockIdx.z * 256 + mrow_base + mf * 16 + h * 8], bp);
            }
        return;
    }

    if (Cbh) {                               // bf16 hi/lo dual output (+bias)
        #pragma unroll
        for (int mf = 0; mf < 4; mf++)
            #pragma unroll
            for (int nf = 0; nf < 4; nf++) {
                int ncol = ncol_base + nf * 8;
                float bx = 0.f, by = 0.f;
                if (bias) { bx = bias[n0 + ncol]; by = bias[n0 + ncol + 1]; }
                #pragma unroll
                for (int h = 0; h < 2; h++) {
                    float vx = acc[mf][nf][h * 2 + 0] + bx;
                    float vy = acc[mf][nf][h * 2 + 1] + by;
                    long row = mrow_base + mf * 16 + h * 8;
                    long e = (n0 / cdiv) * cout + row * (long)ldc + (n0 % cdiv) + ncol;
                    uint32_t ph, pl; split2(vx, vy, ph, pl);
                    *(uint32_t*)(Cbh + e) = ph;
                    *(uint32_t*)(Cbl + e) = pl;
                }
            }
        return;
    }

    float* Cb = C + (long)(n0 / cdiv) * cout;
    long ncb0 = n0 % cdiv;
    #pragma unroll
    for (int mf = 0; mf < 4; mf++)
        #pragma unroll
        for (int nf = 0; nf < 4; nf++) {
            int ncol = ncol_base + nf * 8;
            float bx = 0.f, by = 0.f;
            if (bias) { bx = bias[n0 + ncol]; by = bias[n0 + ncol + 1]; }
            #pragma unroll
            for (int h = 0; h < 2; h++) {
                float vx = acc[mf][nf][h * 2 + 0] + bx;
                float vy = acc[mf][nf][h * 2 + 1] + by;
                if (relu) { vx = fmaxf(vx, 0.f); vy = fmaxf(vy, 0.f); }
                long row = mrow_base + mf * 16 + h * 8;
                *(float2*)&Cb[row * (long)ldc + ncb0 + ncol] = make_float2(vx, vy);
            }
        }
}

// ---------------- merged prep: norms, rearrange, bg2, init, weight conversions ----------------
constexpr int NB_CBN = 1792, NB_W2R = 2560, NB_BG2 = 256, NB_BI = 1;
constexpr int NB_EW2 = 512 * 1280 / 1024;        // 640
constexpr int NB_EW3 = kCH3 * 1536 / 1024;       // 10752
constexpr int NB_CB  = kNCB * kVOC * kDIM / 1024; // 7168

__device__ __forceinline__ void cvt_region(const float* __restrict__ src,
                                           u16* __restrict__ dh, u16* __restrict__ dl,
                                           long base, int tid) {
    long i = base + tid * 4;
    float4 v = *(const float4*)(src + i);
    uint32_t ph0, pl0, ph1, pl1;
    split2(v.x, v.y, ph0, pl0);
    split2(v.z, v.w, ph1, pl1);
    *(uint32_t*)(dh + i) = ph0; *(uint32_t*)(dh + i + 2) = ph1;
    *(uint32_t*)(dl + i) = pl0; *(uint32_t*)(dl + i + 2) = pl1;
}

__global__ void k_prep(const float* __restrict__ cb, const float* __restrict__ dw2,
                       const float* __restrict__ db1, const float* __restrict__ db2,
                       const float* __restrict__ ew2, const float* __restrict__ ew3) {
    int blk = blockIdx.x, tid = threadIdx.x;
    if (blk < NB_CBN) {
        int row = blk * 8 + (tid >> 5), lane = tid & 31;
        const float* p = cb + (long)row * kDIM;
        float acc = 0.f;
        for (int d = lane; d < kDIM; d += 32) { float v = p[d]; acc = fmaf(v, v, acc); }
        #pragma unroll
        for (int o = 16; o > 0; o >>= 1) acc += __shfl_down_sync(0xffffffffu, acc, o);
        if (!lane) g_cbn[row] = acc;
        return;
    }
    blk -= NB_CBN;
    if (blk < NB_W2R) {
        long i = (long)blk * 256 + tid;
        int cp = (int)(i / 2560), r = (int)(i % 2560);
        float v = dw2[(long)cp * 2560 + (r % 512) * 5 + r / 512];
        split1(v, g_W2h[i], g_W2l[i]);
        return;
    }
    blk -= NB_W2R;
    if (blk < NB_BG2) {
        int cp = blk;
        float acc = 0.f;
        for (int kk = tid; kk < 2560; kk += 256)
            acc = fmaf(dw2[(long)cp * 2560 + kk], fmaxf(db1[kk / 5], 0.f), acc);
        __shared__ float red[256];
        red[tid] = acc; __syncthreads();
        for (int st = 128; st; st >>= 1) { if (tid < st) red[tid] += red[tid + st]; __syncthreads(); }
        if (!tid) g_bg2[cp] = fmaxf(red[0] + db2[cp], 0.f);
        return;
    }
    blk -= NB_BG2;
    if (blk < NB_BI) {
        for (int i = tid; i < kNCB * kBS; i += 256) g_best[i] = ~0ull;
        return;
    }
    blk -= NB_BI;
    if (blk < NB_EW2) { cvt_region(ew2, g_ew2h, g_ew2l, (long)blk * 1024, tid); return; }
    blk -= NB_EW2;
    if (blk < NB_EW3) { cvt_region(ew3, g_ew3h, g_ew3l, (long)blk * 1024, tid); return; }
    blk -= NB_EW3;
    cvt_region(cb, g_cbh, g_cbl, (long)blk * 1024, tid);
}

// ---------------- dw1 transpose+convert: [7168][2560] f32 -> [2560][7168] bf16 h/l ----------------
__global__ __launch_bounds__(256) void k_dw1T(const float* __restrict__ dw1) {
    __shared__ float tile[32][33];
    int k0 = blockIdx.x * 32, n0 = blockIdx.y * 32;
    int tid = threadIdx.x;
    int lx = tid & 31, ly = tid >> 5;
    #pragma unroll
    for (int i = 0; i < 4; i++)
        tile[ly + i * 8][lx] = dw1[(long)(k0 + ly + i * 8) * 2560 + n0 + lx];
    __syncthreads();
    int tx = tid & 15, ty = tid >> 4;      // tx -> k pair, ty -> n
    #pragma unroll
    for (int j = 0; j < 2; j++) {
        int n = 2 * ty + j;
        float a = tile[2 * tx][n], b = tile[2 * tx + 1][n];
        uint32_t ph, pl; split2(a, b, ph, pl);
        long e = (long)(n0 + n) * kCH3 + k0 + 2 * tx;
        *(uint32_t*)(g_dw1Th + e) = ph;
        *(uint32_t*)(g_dw1Tl + e) = pl;
    }
}

// ---------------- fill with fused background ----------------
__global__ __launch_bounds__(256) void k_fill(float* __restrict__ out, long n,
                                              const float* __restrict__ dw3,
                                              const float* __restrict__ db3) {
    __shared__ float red[256];
    int c = threadIdx.x;
    float a = 0.f;
    #pragma unroll
    for (int j = 0; j < 7; j++) a += dw3[c * 7 + j];
    red[c] = a * g_bg2[c];
    __syncthreads();
    for (int st = 128; st; st >>= 1) { if (c < st) red[c] += red[c + st]; __syncthreads(); }
    float outv = tanhf(red[0] + db3[0]);
    long i = (long)blockIdx.x * 256 + threadIdx.x;
    if (i < n) out[i] = outv;
}

// ---------------- conv1 window builder (bf16 out) ----------------
__global__ __launch_bounds__(256) void k_prep1(
    const float* __restrict__ audio, const float* __restrict__ ew1, const float* __restrict__ eb1) {
    int m = blockIdx.x; int b = m / kS, s = m % kS;
    int c1 = threadIdx.x;
    float wv[7];
    #pragma unroll
    for (int i = 0; i < 7; i++) wv[i] = ew1[c1 * 7 + i];
    float bias = eb1[c1];
    const float* au = audio + (long)b * kT;
    #pragma unroll
    for (int j = 0; j < 5; j++) {
        int p = s * kHOP - 2 + j;
        float v = 0.f;
        if (p >= 0 && p < kT) {
            float acc = bias;
            #pragma unroll
            for (int i = 0; i < 7; i++) {
                int x = p - 3 + i;
                float a = (x >= 0 && x < kT) ? au[x] : 0.f;
                acc = fmaf(wv[i], a, acc);
            }
            v = fmaxf(acc, 0.f);
        }
        long e = (long)m * 1280 + c1 * 5 + j;
        split1(v, g_S1h[e], g_S1l[e]);
    }
}

// ---------------- im2col: h2p 8-partial reduce + eb2 + relu -> bf16 planes ----------------
__global__ void k_im2col(const float* __restrict__ eb2) {
    int m = blockIdx.x; int b = m / kS, s = m % kS;
    const long SP = (long)kBS * 512;
    for (int kk = threadIdx.x; kk < 1536; kk += blockDim.x) {
        int c2 = kk / 3, j = kk % 3;
        int s2 = s - 1 + j;
        float v = 0.f;
        if (s2 >= 0 && s2 < kS) {
            long idx = (long)(b * kS + s2) * 512 + c2;
            float acc = eb2[c2];
            #pragma unroll
            for (int p = 0; p < 8; p++) acc += g_h2p[idx + p * SP];
            v = fmaxf(acc, 0.f);
        }
        long e = (long)m * 1536 + kk;
        split1(v, g_Xh[e], g_Xl[e]);
    }
}

// ---------------- a-window: C2p 7-partial reduce + db1 + relu -> bf16 planes ----------------
__global__ void k_awin(const float* __restrict__ db1) {
    int m = blockIdx.x; int s = m % kS;
    const long SP = (long)kBS * 2560;
    for (int i = threadIdx.x; i < 13 * 512; i += blockDim.x) {
        int off = i / 512 - 6; int o = i & 511;
        long t = (long)s * kHOP + off;
        float v = 0.f;
        if (t >= 0 && t < kL) {
            if (off >= -2 && off <= 2) {
                long idx = (long)m * 2560 + o * 5 + (off + 2);
                float c2 = 0.f;
                #pragma unroll
                for (int p = 0; p < 7; p++) c2 += g_C2p[idx + p * SP];
                v = fmaxf(c2 + db1[o], 0.f);
            } else v = fmaxf(db1[o], 0.f);
        }
        long e = (long)m * 6656 + i;
        split1(v, g_awh[e], g_awl[e]);
    }
}

// ---------------- final conv3 with fused C3 reduce + db2 + relu ----------------
__global__ __launch_bounds__(256) void k_final(
    float* __restrict__ out, const float* __restrict__ db2,
    const float* __restrict__ dw3, const float* __restrict__ db3) {
    int m = blockIdx.x; int b = m / kS, s = m % kS;
    int tid = threadIdx.x;
    __shared__ float win[9 * 256];
    __shared__ float sbg[256];
    const long SP = 2304L * 256;
    for (int idx = tid; idx < 2304; idx += 256) {
        long base = ((long)m * 9 + idx / 256) * 256 + (idx & 255);
        float v = g_C3p[base] + g_C3p[base + SP] + g_C3p[base + 2 * SP] + g_C3p[base + 3 * SP]
                + db2[idx & 255];
        win[idx] = fmaxf(v, 0.f);
    }
    sbg[tid] = g_bg2[tid];
    __syncthreads();

    int g = tid >> 4, l = tid & 15;
    int r3 = g - 7;
    long t = (long)s * kHOP + r3;
    bool active = (g < 15) && t >= 0 && t < kL;
    float acc = 0.f;
    if (g < 15) {
        for (int c = l; c < 256; c += 16) {
            #pragma unroll
            for (int j = 0; j < 7; j++) {
                int off = r3 - 3 + j;
                long tt = (long)s * kHOP + off;
                float a2;
                if (tt < 0 || tt >= kL) a2 = 0.f;
                else if (off >= -4 && off <= 4) a2 = win[(off + 4) * 256 + c];
                else a2 = sbg[c];
                acc = fmaf(dw3[c * 7 + j], a2, acc);
            }
        }
    }
    #pragma unroll
    for (int o = 8; o > 0; o >>= 1) acc += __shfl_down_sync(0xffffffffu, acc, o, 16);
    if (active && l == 0) out[(long)b * kL + t] = tanhf(acc + db3[0]);
}

// ---------------- launch ----------------
extern "C" void kernel_launch(void* const* d_in, const int* in_sizes, int n_in,
                              void* d_out, int out_size) {
    const float* audio = (const float*)d_in[0];
    const float* cb    = (const float*)d_in[1];
    const float* ew1   = (const float*)d_in[2];
    const float* eb1   = (const float*)d_in[3];
    const float* ew2   = (const float*)d_in[4];
    const float* eb2   = (const float*)d_in[5];
    const float* ew3   = (const float*)d_in[6];
    const float* eb3   = (const float*)d_in[7];
    const float* dw1   = (const float*)d_in[8];
    const float* db1   = (const float*)d_in[9];
    const float* dw2   = (const float*)d_in[10];
    const float* db2   = (const float*)d_in[11];
    const float* dw3   = (const float*)d_in[12];
    const float* db3   = (const float*)d_in[13];
    float* out = (float*)d_out;

    cudaFuncSetAttribute(hmma_gemm<0>, cudaFuncAttributeMaxDynamicSharedMemorySize, SMEM_DYN);
    cudaFuncSetAttribute(hmma_gemm<1>, cudaFuncAttributeMaxDynamicSharedMemorySize, SMEM_DYN);

    void *pS1h, *pS1l, *pE2h, *pE2l, *pXh, *pXl, *pE3h, *pE3l, *pEmh, *pEml;
    void *pCbh, *pCbl, *pD1h, *pD1l, *pW2h, *pW2l, *pAwh, *pAwl;
    void *pH2p, *pC2p, *pC3p, *pCbn, *pBest;
    cudaGetSymbolAddress(&pS1h, g_S1h); cudaGetSymbolAddress(&pS1l, g_S1l);
    cudaGetSymbolAddress(&pE2h, g_ew2h); cudaGetSymbolAddress(&pE2l, g_ew2l);
    cudaGetSymbolAddress(&pXh, g_Xh);   cudaGetSymbolAddress(&pXl, g_Xl);
    cudaGetSymbolAddress(&pE3h, g_ew3h); cudaGetSymbolAddress(&pE3l, g_ew3l);
    cudaGetSymbolAddress(&pEmh, g_embh); cudaGetSymbolAddress(&pEml, g_embl);
    cudaGetSymbolAddress(&pCbh, g_cbh); cudaGetSymbolAddress(&pCbl, g_cbl);
    cudaGetSymbolAddress(&pD1h, g_dw1Th); cudaGetSymbolAddress(&pD1l, g_dw1Tl);
    cudaGetSymbolAddress(&pW2h, g_W2h); cudaGetSymbolAddress(&pW2l, g_W2l);
    cudaGetSymbolAddress(&pAwh, g_awh); cudaGetSymbolAddress(&pAwl, g_awl);
    cudaGetSymbolAddress(&pH2p, g_h2p); cudaGetSymbolAddress(&pC2p, g_C2p);
    cudaGetSymbolAddress(&pC3p, g_C3p); cudaGetSymbolAddress(&pCbn, g_cbn);
    cudaGetSymbolAddress(&pBest, g_best);

    // prep: norms, rearrange+convert, bg2, init, weight conversions, dw1 transpose
    k_prep<<<NB_CBN + NB_W2R + NB_BG2 + NB_BI + NB_EW2 + NB_EW3 + NB_CB, 256>>>(
        cb, dw2, db1, db2, ew2, ew3);
    k_dw1T<<<dim3(kCH3 / 32, 2560 / 32), 256>>>(dw1);
    k_fill<<<(int)((kB * kL + 255) / 256), 256>>>(out, kB * kL, dw3, db3);
    k_prep1<<<kBS, 256>>>(audio, ew1, eb1);

    // encoder conv2: splitK8 -> h2p partials
    hmma_gemm<0><<<dim3(4, 2, 8), 256, SMEM_DYN>>>(
        (const u16*)pS1h, (const u16*)pS1l, (const u16*)pE2h, (const u16*)pE2l,
        (float*)pH2p, 160, 1280, BIGL, 0, 1280, 0, 0, (long)kBS * 512, 160,
        512, BIGL, 0, nullptr, 0, nullptr, nullptr, nullptr, nullptr);
    k_im2col<<<kBS, 256>>>(eb2);
    // encoder conv3 -> emb bf16 planes (+eb3)
    hmma_gemm<0><<<dim3(56, 2, 1), 256, SMEM_DYN>>>(
        (const u16*)pXh, (const u16*)pXl, (const u16*)pE3h, (const u16*)pE3l,
        (float*)pH2p /*dummy*/, 1536, 1536, BIGL, 0, 1536, 0, 0, 0, 0,
        512, 512, (long)kBS * 512, eb3, 0, nullptr, nullptr, (u16*)pEmh, (u16*)pEml);
    // VQ with fused argmin
    hmma_gemm<0><<<dim3(8, 2, 14), 256, SMEM_DYN>>>(
        (const u16*)pEmh, (const u16*)pEml, (const u16*)pCbh, (const u16*)pCbl,
        (float*)pH2p /*dummy*/, 512, 512, BIGL, 0, 512,
        (long)kBS * 512, (long)kVOC * 512, 0, 0,
        512, BIGL, 0, nullptr, 0, (const float*)pCbn, (ull*)pBest, nullptr, nullptr);
    // conv_transpose specials: gathered codebook x dw1T, splitK7
    hmma_gemm<1><<<dim3(20, 2, 7), 256, SMEM_DYN>>>(
        (const u16*)pCbh, (const u16*)pCbl, (const u16*)pD1h, (const u16*)pD1l,
        (float*)pC2p, 1024, kCH3, BIGL, 0, 0, 0, 0, (long)kBS * 2560, 1024,
        2560, BIGL, 0, nullptr, 0, nullptr, nullptr, nullptr, nullptr);
    k_awin<<<kBS, 256>>>(db1);
    // decoder conv2 specials: splitK4 -> C3p partials
    hmma_gemm<0><<<dim3(2, 18, 4), 256, SMEM_DYN>>>(
        (const u16*)pAwh, (const u16*)pAwl, (const u16*)pW2h, (const u16*)pW2l,
        (float*)pC3p, 640, 2560, 9, 6656, 512, 0, 0, 2304L * 256, 640,
        256, BIGL, 0, nullptr, 0, nullptr, nullptr, nullptr, nullptr);
    // final conv3 specials
    k_final<<<kBS, 256>>>(out, db2, dw3, db3);
}

// round 9
// speedup vs baseline: 1.4722x; 1.4722x over previous
#include <cuda_runtime.h>
#include <math.h>
#include <stdint.h>

typedef unsigned long long ull;

// ---------------- problem constants ----------------
constexpr int kB = 2, kT = 98304, kS = 128, kHOP = 768, kNCB = 14;
constexpr int kDIM = 512, kVOC = 1024, kCH3 = kNCB * kDIM;   // 7168
constexpr long kL = 97537;
constexpr int kBS = kB * kS;        // 256
constexpr long BIGL = 1L << 40;

// ---------------- device scratch ----------------
__device__ float g_S1  [kBS * 1280];
__device__ float g_h2p [8 * kBS * 512];
__device__ float g_X   [kBS * 1536];
__device__ float g_emb [kNCB * kBS * kDIM];
__device__ float g_cbn [kNCB * kVOC];
__device__ ull   g_best[kNCB * kBS];            // packed (dist key | code)
__device__ float g_C2p [7 * kBS * 2560];
__device__ float g_awin[kBS * 13 * 512];
__device__ float g_W2r [256 * 2560];
__device__ float g_C3p [4 * 2304 * 256];
__device__ float g_bg2 [256];

// =================== HMMA bf16 split-precision GEMM ===================
constexpr int KC = 32;
constexpr int PITCH_B = 80;
constexpr int TILE_BYTES = 128 * PITCH_B;
constexpr int STAGE = 4 * TILE_BYTES;
constexpr int SMEM_DYN = 2 * STAGE;              // 81920

__device__ __forceinline__ uint32_t s2u(const void* p) {
    uint32_t a;
    asm("{ .reg .u64 t; cvta.to.shared.u64 t, %1; cvt.u32.u64 %0, t; }" : "=r"(a) : "l"(p));
    return a;
}
__device__ __forceinline__ uint32_t pkbf2(float lo, float hi) {
    uint32_t r;
    asm("cvt.rn.bf16x2.f32 %0, %1, %2;" : "=r"(r) : "f"(hi), "f"(lo));
    return r;
}
__device__ __forceinline__ void cvt8(float4 x0, float4 x1, uint4& h, uint4& l) {
    h.x = pkbf2(x0.x, x0.y); h.y = pkbf2(x0.z, x0.w);
    h.z = pkbf2(x1.x, x1.y); h.w = pkbf2(x1.z, x1.w);
    l.x = pkbf2(x0.x - __uint_as_float(h.x << 16), x0.y - __uint_as_float(h.x & 0xffff0000u));
    l.y = pkbf2(x0.z - __uint_as_float(h.y << 16), x0.w - __uint_as_float(h.y & 0xffff0000u));
    l.z = pkbf2(x1.x - __uint_as_float(h.z << 16), x1.y - __uint_as_float(h.z & 0xffff0000u));
    l.w = pkbf2(x1.z - __uint_as_float(h.w << 16), x1.w - __uint_as_float(h.w & 0xffff0000u));
}
__device__ __forceinline__ void ldsm4(uint32_t a, uint32_t& r0, uint32_t& r1,
                                      uint32_t& r2, uint32_t& r3) {
    asm volatile("ldmatrix.sync.aligned.m8n8.x4.shared.b16 {%0,%1,%2,%3},[%4];"
                 : "=r"(r0), "=r"(r1), "=r"(r2), "=r"(r3) : "r"(a));
}
__device__ __forceinline__ void mma16816(float* d, const uint32_t* a, const uint32_t* b) {
    asm volatile(
        "mma.sync.aligned.m16n8k16.row.col.f32.bf16.bf16.f32 "
        "{%0,%1,%2,%3},{%4,%5,%6,%7},{%8,%9},{%0,%1,%2,%3};"
        : "+f"(d[0]), "+f"(d[1]), "+f"(d[2]), "+f"(d[3])
        : "r"(a[0]), "r"(a[1]), "r"(a[2]), "r"(a[3]), "r"(b[0]), "r"(b[1]));
}
__device__ __forceinline__ ull packkey(float f, int n) {
    uint32_t b = __float_as_uint(f);
    uint32_t key = (b & 0x80000000u) ? ~b : (b | 0x80000000u);
    return ((ull)key << 32) | (uint32_t)n;
}
__device__ __forceinline__ ull umin2(ull a, ull b) { return a < b ? a : b; }

// C[m,n] = sum_k A(m)[k]*B(n,k).
// BNN=0: B[N,ldb] row-major. BNN=1: B[K,ldb] row-major AND A is the codebook
// (gather path: A row m of codebook cbk uses code from g_best[cbk*256+m]).
// A row m base = (m/adiv)*aout + (m%adiv)*ain (BNN=0 only).
// z: A+=z*zA, B+=z*zB, C+=z*zC, kbase=z*zK.
// C: Cb = C + (n0/cdiv)*cout; element [mrow*ldc + n0%cdiv + col]; bias[n]; relu.
// If best != nullptr: skip C write; fused VQ argmin using cbn[z*kVOC+n].
template <int BNN>
__global__ __launch_bounds__(256, 1)
void hmma_gemm(const float* __restrict__ A, const float* __restrict__ B,
               float* __restrict__ C, int Klen, int ldb,
               long adiv, long aout, long ain, long zA, long zB, long zC, long zK,
               int ldc, long cdiv, long cout, const float* __restrict__ bias, int relu,
               const float* __restrict__ cbn, ull* __restrict__ best) {
    extern __shared__ __align__(16) char smem[];
    A += (long)blockIdx.z * zA; B += (long)blockIdx.z * zB; C += (long)blockIdx.z * zC;
    long kbase = (long)blockIdx.z * zK;
    int m0 = blockIdx.y * 128, n0 = blockIdx.x * 128;
    int tid = threadIdx.x, lane = tid & 31, wid = tid >> 5;
    int wm = wid & 1, wn = wid >> 1;
    uint32_t sbase = s2u(smem);

    int akg = tid & 3, ar = tid >> 2;
    long arow[2];
    #pragma unroll
    for (int i = 0; i < 2; i++) {
        long m = m0 + ar + i * 64;
        arow[i] = (m / adiv) * aout + (m % adiv) * ain;
    }
    int bkg = tid & 3, br = tid >> 2;
    int bn = tid & 127, bkq = tid >> 7;

    float acc[4][4][4];
    #pragma unroll
    for (int i = 0; i < 4; i++)
        #pragma unroll
        for (int j = 0; j < 4; j++)
            #pragma unroll
            for (int r = 0; r < 4; r++) acc[i][j][r] = 0.f;

    float4 sa[2][2];
    float4 sb[2][2];
    float  sx[16];

#define LOADA(kc) {                                                          \
    if (BNN == 1) {                                                          \
        int cbk = (int)((kc) >> 9), kin = (int)((kc) & 511);                 \
        _Pragma("unroll")                                                    \
        for (int i = 0; i < 2; i++) {                                        \
            uint32_t code = (uint32_t)g_best[cbk * 256 + m0 + ar + i * 64];  \
            const float* p = A + ((long)cbk * kVOC + code) * 512 + kin + akg * 8; \
            sa[i][0] = *(const float4*)p; sa[i][1] = *(const float4*)(p + 4); \
        }                                                                    \
    } else {                                                                 \
        _Pragma("unroll")                                                    \
        for (int i = 0; i < 2; i++) {                                        \
            const float* p = A + arow[i] + (kc) + akg * 8;                   \
            sa[i][0] = *(const float4*)p; sa[i][1] = *(const float4*)(p + 4); \
        }                                                                    \
    } }
#define STSA(buf) {                                                          \
    _Pragma("unroll")                                                        \
    for (int i = 0; i < 2; i++) {                                            \
        uint4 h, l; cvt8(sa[i][0], sa[i][1], h, l);                          \
        uint32_t off = sbase + (buf) * STAGE + (ar + i * 64) * PITCH_B + akg * 16; \
        asm volatile("st.shared.v4.b32 [%0],{%1,%2,%3,%4};" ::               \
            "r"(off), "r"(h.x), "r"(h.y), "r"(h.z), "r"(h.w));               \
        asm volatile("st.shared.v4.b32 [%0],{%1,%2,%3,%4};" ::               \
            "r"(off + TILE_BYTES), "r"(l.x), "r"(l.y), "r"(l.z), "r"(l.w));  \
    } }
#define LOADB_NT(kc) {                                                       \
    _Pragma("unroll")                                                        \
    for (int i = 0; i < 2; i++) {                                            \
        const float* p = B + (long)(n0 + br + i * 64) * ldb + (kc) + bkg * 8; \
        sb[i][0] = *(const float4*)p; sb[i][1] = *(const float4*)(p + 4);    \
    } }
#define STSB_NT(buf) {                                                       \
    _Pragma("unroll")                                                        \
    for (int i = 0; i < 2; i++) {                                            \
        uint4 h, l; cvt8(sb[i][0], sb[i][1], h, l);                          \
        uint32_t off = sbase + (buf) * STAGE + 2 * TILE_BYTES                \
                     + (br + i * 64) * PITCH_B + bkg * 16;                   \
        asm volatile("st.shared.v4.b32 [%0],{%1,%2,%3,%4};" ::               \
            "r"(off), "r"(h.x), "r"(h.y), "r"(h.z), "r"(h.w));               \
        asm volatile("st.shared.v4.b32 [%0],{%1,%2,%3,%4};" ::               \
            "r"(off + TILE_BYTES), "r"(l.x), "r"(l.y), "r"(l.z), "r"(l.w));  \
    } }
#define LOADB_NN(kc) {                                                       \
    _Pragma("unroll")                                                        \
    for (int j = 0; j < 16; j++)                                             \
        sx[j] = B[((kc) + bkq * 16 + j) * (long)ldb + n0 + bn];              \
    }
#define STSB_NN(buf) {                                                       \
    uint32_t off = sbase + (buf) * STAGE + 2 * TILE_BYTES                    \
                 + bn * PITCH_B + bkq * 32;                                  \
    uint4 h, l;                                                              \
    cvt8(make_float4(sx[0], sx[1], sx[2], sx[3]),                            \
         make_float4(sx[4], sx[5], sx[6], sx[7]), h, l);                     \
    asm volatile("st.shared.v4.b32 [%0],{%1,%2,%3,%4};" ::                   \
        "r"(off), "r"(h.x), "r"(h.y), "r"(h.z), "r"(h.w));                   \
    asm volatile("st.shared.v4.b32 [%0],{%1,%2,%3,%4};" ::                   \
        "r"(off + TILE_BYTES), "r"(l.x), "r"(l.y), "r"(l.z), "r"(l.w));      \
    cvt8(make_float4(sx[8], sx[9], sx[10], sx[11]),                          \
         make_float4(sx[12], sx[13], sx[14], sx[15]), h, l);                 \
    asm volatile("st.shared.v4.b32 [%0],{%1,%2,%3,%4};" ::                   \
        "r"(off + 16), "r"(h.x), "r"(h.y), "r"(h.z), "r"(h.w));              \
    asm volatile("st.shared.v4.b32 [%0],{%1,%2,%3,%4};" ::                   \
        "r"(off + TILE_BYTES + 16), "r"(l.x), "r"(l.y), "r"(l.z), "r"(l.w)); \
    }

    LOADA(kbase)
    if (!BNN) { LOADB_NT(kbase) } else { LOADB_NN(kbase) }
    STSA(0)
    if (!BNN) { STSB_NT(0) } else { STSB_NN(0) }
    __syncthreads();

    int T = Klen / KC;
    int j8 = lane >> 3, r8 = lane & 7;
    for (int t = 0; t < T; t++) {
        int cur = t & 1;
        if (t + 1 < T) {
            long kc = kbase + (long)(t + 1) * KC;
            LOADA(kc)
            if (!BNN) { LOADB_NT(kc) } else { LOADB_NN(kc) }
        }
        uint32_t uA = sbase + cur * STAGE;
        uint32_t uB = uA + 2 * TILE_BYTES;
        #pragma unroll
        for (int ks = 0; ks < 2; ks++) {
            uint32_t ah[4][4], al[4][4], bh[4][2], bl[4][2];
            #pragma unroll
            for (int mf = 0; mf < 4; mf++) {
                uint32_t off = (uint32_t)((wm * 64 + mf * 16 + ((j8 & 1) << 3) + r8) * PITCH_B
                                          + ks * 32 + ((j8 >> 1) << 4));
                ldsm4(uA + off, ah[mf][0], ah[mf][1], ah[mf][2], ah[mf][3]);
                ldsm4(uA + TILE_BYTES + off, al[mf][0], al[mf][1], al[mf][2], al[mf][3]);
            }
            #pragma unroll
            for (int fp = 0; fp < 2; fp++) {
                uint32_t off = (uint32_t)((wn * 32 + fp * 16 + ((j8 >> 1) << 3) + r8) * PITCH_B
                                          + ks * 32 + ((j8 & 1) << 4));
                uint32_t t0, t1, t2, t3;
                ldsm4(uB + off, t0, t1, t2, t3);
                bh[fp * 2][0] = t0; bh[fp * 2][1] = t1;
                bh[fp * 2 + 1][0] = t2; bh[fp * 2 + 1][1] = t3;
                ldsm4(uB + TILE_BYTES + off, t0, t1, t2, t3);
                bl[fp * 2][0] = t0; bl[fp * 2][1] = t1;
                bl[fp * 2 + 1][0] = t2; bl[fp * 2 + 1][1] = t3;
            }
            #pragma unroll
            for (int mf = 0; mf < 4; mf++)
                #pragma unroll
                for (int nf = 0; nf < 4; nf++) {
                    mma16816(acc[mf][nf], ah[mf], bh[nf]);
                    mma16816(acc[mf][nf], ah[mf], bl[nf]);
                    mma16816(acc[mf][nf], al[mf], bh[nf]);
                }
        }
        if (t + 1 < T) {
            STSA(1 - cur)
            if (!BNN) { STSB_NT(1 - cur) } else { STSB_NN(1 - cur) }
        }
        __syncthreads();
    }

    int mrow_base = m0 + wm * 64 + (lane >> 2);
    int ncol_base = wn * 32 + (lane & 3) * 2;

    if (best) {
        // fused VQ argmin epilogue
        float cv[8];
        #pragma unroll
        for (int nf = 0; nf < 4; nf++) {
            int ncol = ncol_base + nf * 8;
            cv[nf * 2 + 0] = cbn[(long)blockIdx.z * kVOC + n0 + ncol];
            cv[nf * 2 + 1] = cbn[(long)blockIdx.z * kVOC + n0 + ncol + 1];
        }
        #pragma unroll
        for (int mf = 0; mf < 4; mf++)
            #pragma unroll
            for (int h = 0; h < 2; h++) {
                ull bp = ~0ull;
                #pragma unroll
                for (int nf = 0; nf < 4; nf++) {
                    int ncol = ncol_base + nf * 8;
                    float d0 = cv[nf * 2 + 0] - 2.f * acc[mf][nf][h * 2 + 0];
                    float d1 = cv[nf * 2 + 1] - 2.f * acc[mf][nf][h * 2 + 1];
                    bp = umin2(bp, umin2(packkey(d0, n0 + ncol), packkey(d1, n0 + ncol + 1)));
                }
                bp = umin2(bp, (ull)__shfl_xor_sync(0xffffffffu, (long long)bp, 1));
                bp = umin2(bp, (ull)__shfl_xor_sync(0xffffffffu, (long long)bp, 2));
                if ((lane & 3) == 0)
                    atomicMin(&best[(long)blockIdx.z * 256 + mrow_base + mf * 16 + h * 8], bp);
            }
        return;
    }

    float* Cb = C + (long)(n0 / cdiv) * cout;
    long ncb0 = n0 % cdiv;
    #pragma unroll
    for (int mf = 0; mf < 4; mf++)
        #pragma unroll
        for (int nf = 0; nf < 4; nf++) {
            int ncol = ncol_base + nf * 8;
            float bx = 0.f, by = 0.f;
            if (bias) { bx = bias[n0 + ncol]; by = bias[n0 + ncol + 1]; }
            #pragma unroll
            for (int h = 0; h < 2; h++) {
                float vx = acc[mf][nf][h * 2 + 0] + bx;
                float vy = acc[mf][nf][h * 2 + 1] + by;
                if (relu) { vx = fmaxf(vx, 0.f); vy = fmaxf(vy, 0.f); }
                long row = mrow_base + mf * 16 + h * 8;
                *(float2*)&Cb[row * (long)ldc + ncb0 + ncol] = make_float2(vx, vy);
            }
        }
}

// ---------------- merged prep kernel (weights + conv1 windows) ----------------
constexpr int NB_CBN = 1792, NB_W2R = 2560, NB_BG2 = 256, NB_BI = 1, NB_P1 = kBS;

__global__ void k_prep(const float* __restrict__ cb, const float* __restrict__ dw2,
                       const float* __restrict__ db1, const float* __restrict__ db2,
                       const float* __restrict__ audio, const float* __restrict__ ew1,
                       const float* __restrict__ eb1) {
    int blk = blockIdx.x, tid = threadIdx.x;
    if (blk < NB_CBN) {                    // codebook norms
        int row = blk * 8 + (tid >> 5), lane = tid & 31;
        const float* p = cb + (long)row * kDIM;
        float acc = 0.f;
        for (int d = lane; d < kDIM; d += 32) { float v = p[d]; acc = fmaf(v, v, acc); }
        #pragma unroll
        for (int o = 16; o > 0; o >>= 1) acc += __shfl_down_sync(0xffffffffu, acc, o);
        if (!lane) g_cbn[row] = acc;
        return;
    }
    blk -= NB_CBN;
    if (blk < NB_W2R) {                    // dw2 rearrange
        long i = (long)blk * 256 + tid;
        int cp = (int)(i / 2560), r = (int)(i % 2560);
        g_W2r[i] = dw2[(long)cp * 2560 + (r % 512) * 5 + r / 512];
        return;
    }
    blk -= NB_W2R;
    if (blk < NB_BG2) {                    // bg2
        int cp = blk;
        float acc = 0.f;
        for (int kk = tid; kk < 2560; kk += 256)
            acc = fmaf(dw2[(long)cp * 2560 + kk], fmaxf(db1[kk / 5], 0.f), acc);
        __shared__ float red[256];
        red[tid] = acc; __syncthreads();
        for (int st = 128; st; st >>= 1) { if (tid < st) red[tid] += red[tid + st]; __syncthreads(); }
        if (!tid) g_bg2[cp] = fmaxf(red[0] + db2[cp], 0.f);
        return;
    }
    blk -= NB_BG2;
    if (blk < NB_BI) {                     // init g_best
        for (int i = tid; i < kNCB * kBS; i += 256) g_best[i] = ~0ull;
        return;
    }
    blk -= NB_BI;
    {                                      // conv1 windows (was k_prep1)
        int m = blk; int b = m / kS, s = m % kS;
        int c1 = tid;
        float wv[7];
        #pragma unroll
        for (int i = 0; i < 7; i++) wv[i] = ew1[c1 * 7 + i];
        float bias = eb1[c1];
        const float* au = audio + (long)b * kT;
        #pragma unroll
        for (int j = 0; j < 5; j++) {
            int p = s * kHOP - 2 + j;
            float v = 0.f;
            if (p >= 0 && p < kT) {
                float acc = bias;
                #pragma unroll
                for (int i = 0; i < 7; i++) {
                    int x = p - 3 + i;
                    float a = (x >= 0 && x < kT) ? au[x] : 0.f;
                    acc = fmaf(wv[i], a, acc);
                }
                v = fmaxf(acc, 0.f);
            }
            g_S1[(long)m * 1280 + c1 * 5 + j] = v;
        }
    }
}

// ---------------- fill with fused background compute ----------------
__global__ __launch_bounds__(256) void k_fill(float* __restrict__ out, long n,
                                              const float* __restrict__ dw3,
                                              const float* __restrict__ db3) {
    __shared__ float red[256];
    int c = threadIdx.x;
    float a = 0.f;
    #pragma unroll
    for (int j = 0; j < 7; j++) a += dw3[c * 7 + j];
    red[c] = a * g_bg2[c];
    __syncthreads();
    for (int st = 128; st; st >>= 1) { if (c < st) red[c] += red[c + st]; __syncthreads(); }
    float outv = tanhf(red[0] + db3[0]);
    long i = (long)blockIdx.x * 256 + threadIdx.x;
    if (i < n) out[i] = outv;
}

// ---------------- im2col with fused h2 splitK-reduce + eb2 + relu ----------------
__global__ void k_im2col(const float* __restrict__ eb2) {
    int m = blockIdx.x; int b = m / kS, s = m % kS;
    const long SP = (long)kBS * 512;
    for (int kk = threadIdx.x; kk < 1536; kk += blockDim.x) {
        int c2 = kk / 3, j = kk % 3;
        int s2 = s - 1 + j;
        float v = 0.f;
        if (s2 >= 0 && s2 < kS) {
            long idx = (long)(b * kS + s2) * 512 + c2;
            float acc = eb2[c2];
            #pragma unroll
            for (int p = 0; p < 8; p++) acc += g_h2p[idx + p * SP];
            v = fmaxf(acc, 0.f);
        }
        g_X[(long)m * 1536 + kk] = v;
    }
}

// ---------------- a-window (sums 7 conv_t splitK partials) ----------------
__global__ void k_awin(const float* __restrict__ db1) {
    int m = blockIdx.x; int s = m % kS;
    const long SP = (long)kBS * 2560;
    for (int i = threadIdx.x; i < 13 * 512; i += blockDim.x) {
        int off = i / 512 - 6; int o = i & 511;
        long t = (long)s * kHOP + off;
        float v = 0.f;
        if (t >= 0 && t < kL) {
            if (off >= -2 && off <= 2) {
                long idx = (long)m * 2560 + o * 5 + (off + 2);
                float c2 = 0.f;
                #pragma unroll
                for (int p = 0; p < 7; p++) c2 += g_C2p[idx + p * SP];
                v = fmaxf(c2 + db1[o], 0.f);
            } else v = fmaxf(db1[o], 0.f);
        }
        g_awin[(long)m * 6656 + i] = v;
    }
}

// ---------------- final conv3 with fused C3 splitK-reduce + db2 + relu ----------------
__global__ __launch_bounds__(256) void k_final(
    float* __restrict__ out, const float* __restrict__ db2,
    const float* __restrict__ dw3, const float* __restrict__ db3) {
    int m = blockIdx.x; int b = m / kS, s = m % kS;
    int tid = threadIdx.x;
    __shared__ float win[9 * 256];
    __shared__ float sbg[256];
    const long SP = 2304L * 256;
    for (int idx = tid; idx < 2304; idx += 256) {
        long base = ((long)m * 9 + idx / 256) * 256 + (idx & 255);
        float v = g_C3p[base] + g_C3p[base + SP] + g_C3p[base + 2 * SP] + g_C3p[base + 3 * SP]
                + db2[idx & 255];
        win[idx] = fmaxf(v, 0.f);
    }
    sbg[tid] = g_bg2[tid];
    __syncthreads();

    int g = tid >> 4, l = tid & 15;
    int r3 = g - 7;
    long t = (long)s * kHOP + r3;
    bool active = (g < 15) && t >= 0 && t < kL;
    float acc = 0.f;
    if (g < 15) {
        for (int c = l; c < 256; c += 16) {
            #pragma unroll
            for (int j = 0; j < 7; j++) {
                int off = r3 - 3 + j;
                long tt = (long)s * kHOP + off;
                float a2;
                if (tt < 0 || tt >= kL) a2 = 0.f;
                else if (off >= -4 && off <= 4) a2 = win[(off + 4) * 256 + c];
                else a2 = sbg[c];
                acc = fmaf(dw3[c * 7 + j], a2, acc);
            }
        }
    }
    #pragma unroll
    for (int o = 8; o > 0; o >>= 1) acc += __shfl_down_sync(0xffffffffu, acc, o, 16);
    if (active && l == 0) out[(long)b * kL + t] = tanhf(acc + db3[0]);
}

// ---------------- launch ----------------
extern "C" void kernel_launch(void* const* d_in, const int* in_sizes, int n_in,
                              void* d_out, int out_size) {
    const float* audio = (const float*)d_in[0];
    const float* cb    = (const float*)d_in[1];
    const float* ew1   = (const float*)d_in[2];
    const float* eb1   = (const float*)d_in[3];
    const float* ew2   = (const float*)d_in[4];
    const float* eb2   = (const float*)d_in[5];
    const float* ew3   = (const float*)d_in[6];
    const float* eb3   = (const float*)d_in[7];
    const float* dw1   = (const float*)d_in[8];
    const float* db1   = (const float*)d_in[9];
    const float* dw2   = (const float*)d_in[10];
    const float* db2   = (const float*)d_in[11];
    const float* dw3   = (const float*)d_in[12];
    const float* db3   = (const float*)d_in[13];
    float* out = (float*)d_out;

    cudaFuncSetAttribute(hmma_gemm<0>, cudaFuncAttributeMaxDynamicSharedMemorySize, SMEM_DYN);
    cudaFuncSetAttribute(hmma_gemm<1>, cudaFuncAttributeMaxDynamicSharedMemorySize, SMEM_DYN);

    void *pS1, *pH2p, *pX, *pEmb, *pCbn, *pBest, *pC2p, *pAwin, *pW2r, *pC3p;
    cudaGetSymbolAddress(&pS1, g_S1);   cudaGetSymbolAddress(&pH2p, g_h2p);
    cudaGetSymbolAddress(&pX, g_X);     cudaGetSymbolAddress(&pEmb, g_emb);
    cudaGetSymbolAddress(&pCbn, g_cbn); cudaGetSymbolAddress(&pBest, g_best);
    cudaGetSymbolAddress(&pC2p, g_C2p); cudaGetSymbolAddress(&pAwin, g_awin);
    cudaGetSymbolAddress(&pW2r, g_W2r); cudaGetSymbolAddress(&pC3p, g_C3p);

    // merged prep (cbnorm + w2r + bg2 + best-init + conv1 windows), background fill
    k_prep<<<NB_CBN + NB_W2R + NB_BG2 + NB_BI + NB_P1, 256>>>(
        cb, dw2, db1, db2, audio, ew1, eb1);
    k_fill<<<(int)((kB * kL + 255) / 256), 256>>>(out, kB * kL, dw3, db3);

    // encoder
    hmma_gemm<0><<<dim3(4, 2, 8), 256, SMEM_DYN>>>(
        (const float*)pS1, ew2, (float*)pH2p, 160, 1280,
        BIGL, 0, 1280, 0, 0, (long)kBS * 512, 160, 512, BIGL, 0, nullptr, 0,
        nullptr, nullptr);
    k_im2col<<<kBS, 256>>>(eb2);
    hmma_gemm<0><<<dim3(56, 2, 1), 256, SMEM_DYN>>>(
        (const float*)pX, ew3, (float*)pEmb, 1536, 1536,
        BIGL, 0, 1536, 0, 0, 0, 0, 512, 512, (long)kBS * 512, eb3, 0,
        nullptr, nullptr);

    // VQ with fused argmin
    hmma_gemm<0><<<dim3(8, 2, 14), 256, SMEM_DYN>>>(
        (const float*)pEmb, cb, (float*)pEmb /*unused*/, 512, 512,
        BIGL, 0, 512, (long)kBS * 512, (long)kVOC * 512, 0, 0,
        kVOC, BIGL, 0, nullptr, 0, (const float*)pCbn, (ull*)pBest);

    // decoder conv_transpose specials: gather fused, splitK7 (balanced waves)
    hmma_gemm<1><<<dim3(20, 2, 7), 256, SMEM_DYN>>>(
        cb, dw1, (float*)pC2p, 1024, 2560,
        BIGL, 0, kCH3, 0, 0, (long)kBS * 2560, 1024, 2560, BIGL, 0, nullptr, 0,
        nullptr, nullptr);
    k_awin<<<kBS, 256>>>(db1);

    // decoder conv2 specials: splitK4 (reduce fused into k_final)
    hmma_gemm<0><<<dim3(2, 18, 4), 256, SMEM_DYN>>>(
        (const float*)pAwin, (const float*)pW2r, (float*)pC3p, 640, 2560,
        9, 6656, 512, 0, 0, 2304L * 256, 640, 256, BIGL, 0, nullptr, 0,
        nullptr, nullptr);

    // final conv3 specials (fused reduce + relu)
    k_final<<<kBS, 256>>>(out, db2, dw3, db3);
}

// round 10
// speedup vs baseline: 1.4900x; 1.0121x over previous
#include <cuda_runtime.h>
#include <math.h>
#include <stdint.h>

typedef unsigned long long ull;

// ---------------- problem constants ----------------
constexpr int kB = 2, kT = 98304, kS = 128, kHOP = 768, kNCB = 14;
constexpr int kDIM = 512, kVOC = 1024, kCH3 = kNCB * kDIM;   // 7168
constexpr long kL = 97537;
constexpr int kBS = kB * kS;        // 256
constexpr long BIGL = 1L << 40;

// ---------------- device scratch ----------------
__device__ float g_S1  [kBS * 1280];
__device__ float g_h2p [8 * kBS * 512];
__device__ float g_X   [kBS * 1536];
__device__ float g_emb [kNCB * kBS * kDIM];
__device__ float g_cbn [kNCB * kVOC];
__device__ ull   g_best[kNCB * kBS];            // packed (dist key | code)
__device__ float g_C2p [7 * kBS * 2560];
__device__ float g_awin[kBS * 13 * 512];
__device__ float g_W2r [256 * 2560];
__device__ float g_C3p [4 * 2304 * 256];
__device__ float g_bg2 [256];

// =================== HMMA bf16 split-precision GEMM ===================
constexpr int KC = 32;
constexpr int PITCH_B = 80;
constexpr int TILE_BYTES = 128 * PITCH_B;
constexpr int STAGE = 4 * TILE_BYTES;
constexpr int SMEM_DYN = 2 * STAGE;              // 81920

__device__ __forceinline__ uint32_t s2u(const void* p) {
    uint32_t a;
    asm("{ .reg .u64 t; cvta.to.shared.u64 t, %1; cvt.u32.u64 %0, t; }" : "=r"(a) : "l"(p));
    return a;
}
__device__ __forceinline__ uint32_t pkbf2(float lo, float hi) {
    uint32_t r;
    asm("cvt.rn.bf16x2.f32 %0, %1, %2;" : "=r"(r) : "f"(hi), "f"(lo));
    return r;
}
__device__ __forceinline__ void cvt8(float4 x0, float4 x1, uint4& h, uint4& l) {
    h.x = pkbf2(x0.x, x0.y); h.y = pkbf2(x0.z, x0.w);
    h.z = pkbf2(x1.x, x1.y); h.w = pkbf2(x1.z, x1.w);
    l.x = pkbf2(x0.x - __uint_as_float(h.x << 16), x0.y - __uint_as_float(h.x & 0xffff0000u));
    l.y = pkbf2(x0.z - __uint_as_float(h.y << 16), x0.w - __uint_as_float(h.y & 0xffff0000u));
    l.z = pkbf2(x1.x - __uint_as_float(h.z << 16), x1.y - __uint_as_float(h.z & 0xffff0000u));
    l.w = pkbf2(x1.z - __uint_as_float(h.w << 16), x1.w - __uint_as_float(h.w & 0xffff0000u));
}
__device__ __forceinline__ void ldsm4(uint32_t a, uint32_t& r0, uint32_t& r1,
                                      uint32_t& r2, uint32_t& r3) {
    asm volatile("ldmatrix.sync.aligned.m8n8.x4.shared.b16 {%0,%1,%2,%3},[%4];"
                 : "=r"(r0), "=r"(r1), "=r"(r2), "=r"(r3) : "r"(a));
}
__device__ __forceinline__ void mma16816(float* d, const uint32_t* a, const uint32_t* b) {
    asm volatile(
        "mma.sync.aligned.m16n8k16.row.col.f32.bf16.bf16.f32 "
        "{%0,%1,%2,%3},{%4,%5,%6,%7},{%8,%9},{%0,%1,%2,%3};"
        : "+f"(d[0]), "+f"(d[1]), "+f"(d[2]), "+f"(d[3])
        : "r"(a[0]), "r"(a[1]), "r"(a[2]), "r"(a[3]), "r"(b[0]), "r"(b[1]));
}
__device__ __forceinline__ ull packkey(float f, int n) {
    uint32_t b = __float_as_uint(f);
    uint32_t key = (b & 0x80000000u) ? ~b : (b | 0x80000000u);
    return ((ull)key << 32) | (uint32_t)n;
}
__device__ __forceinline__ ull umin2(ull a, ull b) { return a < b ? a : b; }

// C[m,n] = sum_k A(m)[k]*B(n,k).
// BNN=0: B[N,ldb] row-major. BNN=1: B[K,ldb] row-major AND A is the codebook
// (gather path: A row m of codebook cbk uses code from g_best[cbk*256+m]).
// A row m base = (m/adiv)*aout + (m%adiv)*ain (BNN=0 only).
// z: A+=z*zA, B+=z*zB, C+=z*zC, kbase=z*zK.
// C: Cb = C + (n0/cdiv)*cout; element [mrow*ldc + n0%cdiv + col]; bias[n]; relu.
// If best != nullptr: skip C write; fused VQ argmin using cbn[z*kVOC+n].
template <int BNN>
__global__ __launch_bounds__(256, 1)
void hmma_gemm(const float* __restrict__ A, const float* __restrict__ B,
               float* __restrict__ C, int Klen, int ldb,
               long adiv, long aout, long ain, long zA, long zB, long zC, long zK,
               int ldc, long cdiv, long cout, const float* __restrict__ bias, int relu,
               const float* __restrict__ cbn, ull* __restrict__ best) {
    extern __shared__ __align__(16) char smem[];
    A += (long)blockIdx.z * zA; B += (long)blockIdx.z * zB; C += (long)blockIdx.z * zC;
    long kbase = (long)blockIdx.z * zK;
    int m0 = blockIdx.y * 128, n0 = blockIdx.x * 128;
    int tid = threadIdx.x, lane = tid & 31, wid = tid >> 5;
    int wm = wid & 1, wn = wid >> 1;
    uint32_t sbase = s2u(smem);

    int akg = tid & 3, ar = tid >> 2;
    long arow[2];
    #pragma unroll
    for (int i = 0; i < 2; i++) {
        long m = m0 + ar + i * 64;
        arow[i] = (m / adiv) * aout + (m % adiv) * ain;
    }
    int bkg = tid & 3, br = tid >> 2;
    int bn = tid & 127, bkq = tid >> 7;

    float acc[4][4][4];
    #pragma unroll
    for (int i = 0; i < 4; i++)
        #pragma unroll
        for (int j = 0; j < 4; j++)
            #pragma unroll
            for (int r = 0; r < 4; r++) acc[i][j][r] = 0.f;

    float4 sa[2][2];
    float4 sb[2][2];
    float  sx[16];

#define LOADA(kc) {                                                          \
    if (BNN == 1) {                                                          \
        int cbk = (int)((kc) >> 9), kin = (int)((kc) & 511);                 \
        _Pragma("unroll")                                                    \
        for (int i = 0; i < 2; i++) {                                        \
            uint32_t code = (uint32_t)g_best[cbk * 256 + m0 + ar + i * 64];  \
            const float* p = A + ((long)cbk * kVOC + code) * 512 + kin + akg * 8; \
            sa[i][0] = *(const float4*)p; sa[i][1] = *(const float4*)(p + 4); \
        }                                                                    \
    } else {                                                                 \
        _Pragma("unroll")                                                    \
        for (int i = 0; i < 2; i++) {                                        \
            const float* p = A + arow[i] + (kc) + akg * 8;                   \
            sa[i][0] = *(const float4*)p; sa[i][1] = *(const float4*)(p + 4); \
        }                                                                    \
    } }
#define STSA(buf) {                                                          \
    _Pragma("unroll")                                                        \
    for (int i = 0; i < 2; i++) {                                            \
        uint4 h, l; cvt8(sa[i][0], sa[i][1], h, l);                          \
        uint32_t off = sbase + (buf) * STAGE + (ar + i * 64) * PITCH_B + akg * 16; \
        asm volatile("st.shared.v4.b32 [%0],{%1,%2,%3,%4};" ::               \
            "r"(off), "r"(h.x), "r"(h.y), "r"(h.z), "r"(h.w));               \
        asm volatile("st.shared.v4.b32 [%0],{%1,%2,%3,%4};" ::               \
            "r"(off + TILE_BYTES), "r"(l.x), "r"(l.y), "r"(l.z), "r"(l.w));  \
    } }
#define LOADB_NT(kc) {                                                       \
    _Pragma("unroll")                                                        \
    for (int i = 0; i < 2; i++) {                                            \
        const float* p = B + (long)(n0 + br + i * 64) * ldb + (kc) + bkg * 8; \
        sb[i][0] = *(const float4*)p; sb[i][1] = *(const float4*)(p + 4);    \
    } }
#define STSB_NT(buf) {                                                       \
    _Pragma("unroll")                                                        \
    for (int i = 0; i < 2; i++) {                                            \
        uint4 h, l; cvt8(sb[i][0], sb[i][1], h, l);                          \
        uint32_t off = sbase + (buf) * STAGE + 2 * TILE_BYTES                \
                     + (br + i * 64) * PITCH_B + bkg * 16;                   \
        asm volatile("st.shared.v4.b32 [%0],{%1,%2,%3,%4};" ::               \
            "r"(off), "r"(h.x), "r"(h.y), "r"(h.z), "r"(h.w));               \
        asm volatile("st.shared.v4.b32 [%0],{%1,%2,%3,%4};" ::               \
            "r"(off + TILE_BYTES), "r"(l.x), "r"(l.y), "r"(l.z), "r"(l.w));  \
    } }
#define LOADB_NN(kc) {                                                       \
    _Pragma("unroll")                                                        \
    for (int j = 0; j < 16; j++)                                             \
        sx[j] = B[((kc) + bkq * 16 + j) * (long)ldb + n0 + bn];              \
    }
#define STSB_NN(buf) {                                                       \
    uint32_t off = sbase + (buf) * STAGE + 2 * TILE_BYTES                    \
                 + bn * PITCH_B + bkq * 32;                                  \
    uint4 h, l;                                                              \
    cvt8(make_float4(sx[0], sx[1], sx[2], sx[3]),                            \
         make_float4(sx[4], sx[5], sx[6], sx[7]), h, l);                     \
    asm volatile("st.shared.v4.b32 [%0],{%1,%2,%3,%4};" ::                   \
        "r"(off), "r"(h.x), "r"(h.y), "r"(h.z), "r"(h.w));                   \
    asm volatile("st.shared.v4.b32 [%0],{%1,%2,%3,%4};" ::                   \
        "r"(off + TILE_BYTES), "r"(l.x), "r"(l.y), "r"(l.z), "r"(l.w));      \
    cvt8(make_float4(sx[8], sx[9], sx[10], sx[11]),                          \
         make_float4(sx[12], sx[13], sx[14], sx[15]), h, l);                 \
    asm volatile("st.shared.v4.b32 [%0],{%1,%2,%3,%4};" ::                   \
        "r"(off + 16), "r"(h.x), "r"(h.y), "r"(h.z), "r"(h.w));              \
    asm volatile("st.shared.v4.b32 [%0],{%1,%2,%3,%4};" ::                   \
        "r"(off + TILE_BYTES + 16), "r"(l.x), "r"(l.y), "r"(l.z), "r"(l.w)); \
    }

    LOADA(kbase)
    if (!BNN) { LOADB_NT(kbase) } else { LOADB_NN(kbase) }
    STSA(0)
    if (!BNN) { STSB_NT(0) } else { STSB_NN(0) }
    __syncthreads();

    int T = Klen / KC;
    int j8 = lane >> 3, r8 = lane & 7;
    for (int t = 0; t < T; t++) {
        int cur = t & 1;
        if (t + 1 < T) {
            long kc = kbase + (long)(t + 1) * KC;
            LOADA(kc)
            if (!BNN) { LOADB_NT(kc) } else { LOADB_NN(kc) }
        }
        uint32_t uA = sbase + cur * STAGE;
        uint32_t uB = uA + 2 * TILE_BYTES;
        #pragma unroll
        for (int ks = 0; ks < 2; ks++) {
            uint32_t ah[4][4], al[4][4], bh[4][2], bl[4][2];
            #pragma unroll
            for (int mf = 0; mf < 4; mf++) {
                uint32_t off = (uint32_t)((wm * 64 + mf * 16 + ((j8 & 1) << 3) + r8) * PITCH_B
                                          + ks * 32 + ((j8 >> 1) << 4));
                ldsm4(uA + off, ah[mf][0], ah[mf][1], ah[mf][2], ah[mf][3]);
                ldsm4(uA + TILE_BYTES + off, al[mf][0], al[mf][1], al[mf][2], al[mf][3]);
            }
            #pragma unroll
            for (int fp = 0; fp < 2; fp++) {
                uint32_t off = (uint32_t)((wn * 32 + fp * 16 + ((j8 >> 1) << 3) + r8) * PITCH_B
                                          + ks * 32 + ((j8 & 1) << 4));
                uint32_t t0, t1, t2, t3;
                ldsm4(uB + off, t0, t1, t2, t3);
                bh[fp * 2][0] = t0; bh[fp * 2][1] = t1;
                bh[fp * 2 + 1][0] = t2; bh[fp * 2 + 1][1] = t3;
                ldsm4(uB + TILE_BYTES + off, t0, t1, t2, t3);
                bl[fp * 2][0] = t0; bl[fp * 2][1] = t1;
                bl[fp * 2 + 1][0] = t2; bl[fp * 2 + 1][1] = t3;
            }
            #pragma unroll
            for (int mf = 0; mf < 4; mf++)
                #pragma unroll
                for (int nf = 0; nf < 4; nf++) {
                    mma16816(acc[mf][nf], ah[mf], bh[nf]);
                    mma16816(acc[mf][nf], ah[mf], bl[nf]);
                    mma16816(acc[mf][nf], al[mf], bh[nf]);
                }
        }
        if (t + 1 < T) {
            STSA(1 - cur)
            if (!BNN) { STSB_NT(1 - cur) } else { STSB_NN(1 - cur) }
        }
        __syncthreads();
    }

    int mrow_base = m0 + wm * 64 + (lane >> 2);
    int ncol_base = wn * 32 + (lane & 3) * 2;

    if (best) {
        // fused VQ argmin epilogue
        float cv[8];
        #pragma unroll
        for (int nf = 0; nf < 4; nf++) {
            int ncol = ncol_base + nf * 8;
            cv[nf * 2 + 0] = cbn[(long)blockIdx.z * kVOC + n0 + ncol];
            cv[nf * 2 + 1] = cbn[(long)blockIdx.z * kVOC + n0 + ncol + 1];
        }
        #pragma unroll
        for (int mf = 0; mf < 4; mf++)
            #pragma unroll
            for (int h = 0; h < 2; h++) {
                ull bp = ~0ull;
                #pragma unroll
                for (int nf = 0; nf < 4; nf++) {
                    int ncol = ncol_base + nf * 8;
                    float d0 = cv[nf * 2 + 0] - 2.f * acc[mf][nf][h * 2 + 0];
                    float d1 = cv[nf * 2 + 1] - 2.f * acc[mf][nf][h * 2 + 1];
                    bp = umin2(bp, umin2(packkey(d0, n0 + ncol), packkey(d1, n0 + ncol + 1)));
                }
                bp = umin2(bp, (ull)__shfl_xor_sync(0xffffffffu, (long long)bp, 1));
                bp = umin2(bp, (ull)__shfl_xor_sync(0xffffffffu, (long long)bp, 2));
                if ((lane & 3) == 0)
                    atomicMin(&best[(long)blockIdx.z * 256 + mrow_base + mf * 16 + h * 8], bp);
            }
        return;
    }

    float* Cb = C + (long)(n0 / cdiv) * cout;
    long ncb0 = n0 % cdiv;
    #pragma unroll
    for (int mf = 0; mf < 4; mf++)
        #pragma unroll
        for (int nf = 0; nf < 4; nf++) {
            int ncol = ncol_base + nf * 8;
            float bx = 0.f, by = 0.f;
            if (bias) { bx = bias[n0 + ncol]; by = bias[n0 + ncol + 1]; }
            #pragma unroll
            for (int h = 0; h < 2; h++) {
                float vx = acc[mf][nf][h * 2 + 0] + bx;
                float vy = acc[mf][nf][h * 2 + 1] + by;
                if (relu) { vx = fmaxf(vx, 0.f); vy = fmaxf(vy, 0.f); }
                long row = mrow_base + mf * 16 + h * 8;
                *(float2*)&Cb[row * (long)ldc + ncb0 + ncol] = make_float2(vx, vy);
            }
        }
}

// ---------------- merged prep kernel (weights + conv1 windows) ----------------
constexpr int NB_CBN = 1792, NB_W2R = 2560, NB_BG2 = 256, NB_BI = 1, NB_P1 = kBS;

__global__ void k_prep(const float* __restrict__ cb, const float* __restrict__ dw2,
                       const float* __restrict__ db1, const float* __restrict__ db2,
                       const float* __restrict__ audio, const float* __restrict__ ew1,
                       const float* __restrict__ eb1) {
    int blk = blockIdx.x, tid = threadIdx.x;
    if (blk < NB_CBN) {                    // codebook norms
        int row = blk * 8 + (tid >> 5), lane = tid & 31;
        const float* p = cb + (long)row * kDIM;
        float acc = 0.f;
        for (int d = lane; d < kDIM; d += 32) { float v = p[d]; acc = fmaf(v, v, acc); }
        #pragma unroll
        for (int o = 16; o > 0; o >>= 1) acc += __shfl_down_sync(0xffffffffu, acc, o);
        if (!lane) g_cbn[row] = acc;
        return;
    }
    blk -= NB_CBN;
    if (blk < NB_W2R) {                    // dw2 rearrange
        long i = (long)blk * 256 + tid;
        int cp = (int)(i / 2560), r = (int)(i % 2560);
        g_W2r[i] = dw2[(long)cp * 2560 + (r % 512) * 5 + r / 512];
        return;
    }
    blk -= NB_W2R;
    if (blk < NB_BG2) {                    // bg2
        int cp = blk;
        float acc = 0.f;
        for (int kk = tid; kk < 2560; kk += 256)
            acc = fmaf(dw2[(long)cp * 2560 + kk], fmaxf(db1[kk / 5], 0.f), acc);
        __shared__ float red[256];
        red[tid] = acc; __syncthreads();
        for (int st = 128; st; st >>= 1) { if (tid < st) red[tid] += red[tid + st]; __syncthreads(); }
        if (!tid) g_bg2[cp] = fmaxf(red[0] + db2[cp], 0.f);
        return;
    }
    blk -= NB_BG2;
    if (blk < NB_BI) {                     // init g_best
        for (int i = tid; i < kNCB * kBS; i += 256) g_best[i] = ~0ull;
        return;
    }
    blk -= NB_BI;
    {                                      // conv1 windows
        int m = blk; int b = m / kS, s = m % kS;
        int c1 = tid;
        float wv[7];
        #pragma unroll
        for (int i = 0; i < 7; i++) wv[i] = ew1[c1 * 7 + i];
        float bias = eb1[c1];
        const float* au = audio + (long)b * kT;
        #pragma unroll
        for (int j = 0; j < 5; j++) {
            int p = s * kHOP - 2 + j;
            float v = 0.f;
            if (p >= 0 && p < kT) {
                float acc = bias;
                #pragma unroll
                for (int i = 0; i < 7; i++) {
                    int x = p - 3 + i;
                    float a = (x >= 0 && x < kT) ? au[x] : 0.f;
                    acc = fmaf(wv[i], a, acc);
                }
                v = fmaxf(acc, 0.f);
            }
            g_S1[(long)m * 1280 + c1 * 5 + j] = v;
        }
    }
}

// ---------------- fill with fused background compute ----------------
__global__ __launch_bounds__(256) void k_fill(float* __restrict__ out, long n,
                                              const float* __restrict__ dw3,
                                              const float* __restrict__ db3) {
    __shared__ float red[256];
    int c = threadIdx.x;
    float a = 0.f;
    #pragma unroll
    for (int j = 0; j < 7; j++) a += dw3[c * 7 + j];
    red[c] = a * g_bg2[c];
    __syncthreads();
    for (int st = 128; st; st >>= 1) { if (c < st) red[c] += red[c + st]; __syncthreads(); }
    float outv = tanhf(red[0] + db3[0]);
    long i = (long)blockIdx.x * 256 + threadIdx.x;
    if (i < n) out[i] = outv;
}

// ---------------- im2col: smem-staged h2 reduce + window emit ----------------
__global__ __launch_bounds__(256) void k_im2col(const float* __restrict__ eb2) {
    int m = blockIdx.x; int b = m / kS, s = m % kS;
    __shared__ float sh[3][520];
    const long SP = (long)kBS * 512;
    int tid = threadIdx.x;
    int c2 = tid * 2;
    #pragma unroll
    for (int r = 0; r < 3; r++) {
        int s2 = s - 1 + r;
        float vx = 0.f, vy = 0.f;
        if (s2 >= 0 && s2 < kS) {
            long idx = (long)(b * kS + s2) * 512 + c2;
            float ax = eb2[c2], ay = eb2[c2 + 1];
            #pragma unroll
            for (int p = 0; p < 8; p++) {
                float2 t = *(const float2*)&g_h2p[idx + p * SP];
                ax += t.x; ay += t.y;
            }
            vx = fmaxf(ax, 0.f); vy = fmaxf(ay, 0.f);
        }
        sh[r][c2] = vx; sh[r][c2 + 1] = vy;
    }
    __syncthreads();
    #pragma unroll
    for (int it = 0; it < 6; it++) {
        int kk = it * 256 + tid;
        g_X[(long)m * 1536 + kk] = sh[kk % 3][kk / 3];
    }
}

// ---------------- a-window: smem-staged full-row C2p reduce ----------------
__global__ __launch_bounds__(256) void k_awin(const float* __restrict__ db1) {
    int m = blockIdx.x; int s = m % kS;
    __shared__ float sum[2560];
    const long SP = (long)kBS * 2560;
    int tid = threadIdx.x;
    #pragma unroll
    for (int it = 0; it < 3; it++) {
        int i = it * 1024 + tid * 4;
        if (i < 2560) {
            long idx = (long)m * 2560 + i;
            float4 a = make_float4(0.f, 0.f, 0.f, 0.f);
            #pragma unroll
            for (int p = 0; p < 7; p++) {
                float4 t = *(const float4*)&g_C2p[idx + p * SP];
                a.x += t.x; a.y += t.y; a.z += t.z; a.w += t.w;
            }
            *(float4*)&sum[i] = a;
        }
    }
    __syncthreads();
    for (int i = tid; i < 13 * 512; i += 256) {
        int off = i / 512 - 6; int o = i & 511;
        long t = (long)s * kHOP + off;
        float v = 0.f;
        if (t >= 0 && t < kL) {
            if (off >= -2 && off <= 2)
                v = fmaxf(sum[o * 5 + (off + 2)] + db1[o], 0.f);
            else v = fmaxf(db1[o], 0.f);
        }
        g_awin[(long)m * 6656 + i] = v;
    }
}

// ---------------- final conv3 with fused C3 splitK-reduce + db2 + relu ----------------
__global__ __launch_bounds__(256) void k_final(
    float* __restrict__ out, const float* __restrict__ db2,
    const float* __restrict__ dw3, const float* __restrict__ db3) {
    int m = blockIdx.x; int b = m / kS, s = m % kS;
    int tid = threadIdx.x;
    __shared__ float win[9 * 256];
    __shared__ float sbg[256];
    const long SP = 2304L * 256;
    for (int idx = tid; idx < 2304; idx += 256) {
        long base = ((long)m * 9 + idx / 256) * 256 + (idx & 255);
        float v = g_C3p[base] + g_C3p[base + SP] + g_C3p[base + 2 * SP] + g_C3p[base + 3 * SP]
                + db2[idx & 255];
        win[idx] = fmaxf(v, 0.f);
    }
    sbg[tid] = g_bg2[tid];
    __syncthreads();

    int g = tid >> 4, l = tid & 15;
    int r3 = g - 7;
    long t = (long)s * kHOP + r3;
    bool active = (g < 15) && t >= 0 && t < kL;
    float acc = 0.f;
    if (g < 15) {
        for (int c = l; c < 256; c += 16) {
            #pragma unroll
            for (int j = 0; j < 7; j++) {
                int off = r3 - 3 + j;
                long tt = (long)s * kHOP + off;
                float a2;
                if (tt < 0 || tt >= kL) a2 = 0.f;
                else if (off >= -4 && off <= 4) a2 = win[(off + 4) * 256 + c];
                else a2 = sbg[c];
                acc = fmaf(dw3[c * 7 + j], a2, acc);
            }
        }
    }
    #pragma unroll
    for (int o = 8; o > 0; o >>= 1) acc += __shfl_down_sync(0xffffffffu, acc, o, 16);
    if (active && l == 0) out[(long)b * kL + t] = tanhf(acc + db3[0]);
}

// ---------------- launch ----------------
extern "C" void kernel_launch(void* const* d_in, const int* in_sizes, int n_in,
                              void* d_out, int out_size) {
    const float* audio = (const float*)d_in[0];
    const float* cb    = (const float*)d_in[1];
    const float* ew1   = (const float*)d_in[2];
    const float* eb1   = (const float*)d_in[3];
    const float* ew2   = (const float*)d_in[4];
    const float* eb2   = (const float*)d_in[5];
    const float* ew3   = (const float*)d_in[6];
    const float* eb3   = (const float*)d_in[7];
    const float* dw1   = (const float*)d_in[8];
    const float* db1   = (const float*)d_in[9];
    const float* dw2   = (const float*)d_in[10];
    const float* db2   = (const float*)d_in[11];
    const float* dw3   = (const float*)d_in[12];
    const float* db3   = (const float*)d_in[13];
    float* out = (float*)d_out;

    cudaFuncSetAttribute(hmma_gemm<0>, cudaFuncAttributeMaxDynamicSharedMemorySize, SMEM_DYN);
    cudaFuncSetAttribute(hmma_gemm<1>, cudaFuncAttributeMaxDynamicSharedMemorySize, SMEM_DYN);

    void *pS1, *pH2p, *pX, *pEmb, *pCbn, *pBest, *pC2p, *pAwin, *pW2r, *pC3p;
    cudaGetSymbolAddress(&pS1, g_S1);   cudaGetSymbolAddress(&pH2p, g_h2p);
    cudaGetSymbolAddress(&pX, g_X);     cudaGetSymbolAddress(&pEmb, g_emb);
    cudaGetSymbolAddress(&pCbn, g_cbn); cudaGetSymbolAddress(&pBest, g_best);
    cudaGetSymbolAddress(&pC2p, g_C2p); cudaGetSymbolAddress(&pAwin, g_awin);
    cudaGetSymbolAddress(&pW2r, g_W2r); cudaGetSymbolAddress(&pC3p, g_C3p);

    // merged prep (cbnorm + w2r + bg2 + best-init + conv1 windows), background fill
    k_prep<<<NB_CBN + NB_W2R + NB_BG2 + NB_BI + NB_P1, 256>>>(
        cb, dw2, db1, db2, audio, ew1, eb1);
    k_fill<<<(int)((kB * kL + 255) / 256), 256>>>(out, kB * kL, dw3, db3);

    // encoder
    hmma_gemm<0><<<dim3(4, 2, 8), 256, SMEM_DYN>>>(
        (const float*)pS1, ew2, (float*)pH2p, 160, 1280,
        BIGL, 0, 1280, 0, 0, (long)kBS * 512, 160, 512, BIGL, 0, nullptr, 0,
        nullptr, nullptr);
    k_im2col<<<kBS, 256>>>(eb2);
    hmma_gemm<0><<<dim3(56, 2, 1), 256, SMEM_DYN>>>(
        (const float*)pX, ew3, (float*)pEmb, 1536, 1536,
        BIGL, 0, 1536, 0, 0, 0, 0, 512, 512, (long)kBS * 512, eb3, 0,
        nullptr, nullptr);

    // VQ with fused argmin
    hmma_gemm<0><<<dim3(8, 2, 14), 256, SMEM_DYN>>>(
        (const float*)pEmb, cb, (float*)pEmb /*unused*/, 512, 512,
        BIGL, 0, 512, (long)kBS * 512, (long)kVOC * 512, 0, 0,
        kVOC, BIGL, 0, nullptr, 0, (const float*)pCbn, (ull*)pBest);

    // decoder conv_transpose specials: gather fused, splitK7 (balanced waves)
    hmma_gemm<1><<<dim3(20, 2, 7), 256, SMEM_DYN>>>(
        cb, dw1, (float*)pC2p, 1024, 2560,
        BIGL, 0, kCH3, 0, 0, (long)kBS * 2560, 1024, 2560, BIGL, 0, nullptr, 0,
        nullptr, nullptr);
    k_awin<<<kBS, 256>>>(db1);

    // decoder conv2 specials: splitK4 (reduce fused into k_final)
    hmma_gemm<0><<<dim3(2, 18, 4), 256, SMEM_DYN>>>(
        (const float*)pAwin, (const float*)pW2r, (float*)pC3p, 640, 2560,
        9, 6656, 512, 0, 0, 2304L * 256, 640, 256, BIGL, 0, nullptr, 0,
        nullptr, nullptr);

    // final conv3 specials (fused reduce + relu)
    k_final<<<kBS, 256>>>(out, db2, dw3, db3);
}